// round 7
// baseline (speedup 1.0000x reference)
#include <cuda_runtime.h>

// PixelShuffle / depth-to-space, R=2, feature-major grouping.
// in : [B=8, X=256, Y=256, C=256] fp32
// out: [B, 2X=512, 2Y=512, F=64]  fp32
// out[b, 2x+i, 2y+j, f] = in[b, x, y, 4f + 2i + j]
//
// 256-bit variant (sm_100+ ld/st.global.v8.f32): 8 threads per input pixel.
// Thread t loads channels [32t, 32t+32) as 4x LDG.256 (warp = 4KB contiguous),
// emits one STG.256 per (i,j) phase: features 8t..8t+7, 8 threads cover a
// full 256B output row; per i-phase a warp's stores span 2KB contiguous.
// Channel 32t+8q+r -> v[q][r]; phase ph feature 8t+m <- v[m/2][(m%2)*4+ph].
// History: .cs hints regressed (L1 churn); persistent loop regressed (serialized
// MLP); occ 49% with 2x MLP neutral -> DRAM ~86% is the recurring ceiling.

static constexpr int X = 256;
static constexpr int Y = 256;
static constexpr int THREADS = 256;

__global__ void __launch_bounds__(THREADS)
pixel_shuffle_kernel(const float* __restrict__ in, float* __restrict__ out) {
    const unsigned g = blockIdx.x * THREADS + threadIdx.x;
    const unsigned t = g & 7u;            // 32-channel chunk within pixel
    const unsigned p = g >> 3;            // input pixel id: b*65536 + x*256 + y

    const unsigned y = p & 255u;
    const unsigned x = (p >> 8) & 255u;
    const unsigned b = p >> 16;

    // ---- load: 32 contiguous channels = 4 x 256-bit ----
    const float* ip = in + (size_t)p * 256 + t * 32;
    float v[4][8];
#pragma unroll
    for (int q = 0; q < 4; q++) {
        asm volatile("ld.global.v8.f32 {%0,%1,%2,%3,%4,%5,%6,%7}, [%8];"
                     : "=f"(v[q][0]), "=f"(v[q][1]), "=f"(v[q][2]), "=f"(v[q][3]),
                       "=f"(v[q][4]), "=f"(v[q][5]), "=f"(v[q][6]), "=f"(v[q][7])
                     : "l"(ip + q * 8));
    }

    // ---- store: one 256-bit per (i,j) phase ----
    // out float index base (i=j=0): ((b*512 + 2x)*512 + 2y)*64 + 8t
    const unsigned obase = (((b * (2 * X) + 2 * x) * (2 * Y)) + 2 * y) * 64 + t * 8;
    const unsigned ROWI = (2 * Y) * 64;   // +i: one output X-row (32768 floats)
    const unsigned ROWJ = 64;             // +j: one output Y-row

    const unsigned off[4] = {0u, ROWJ, ROWI, ROWI + ROWJ};  // ph = 2i + j
#pragma unroll
    for (int ph = 0; ph < 4; ph++) {
        float* op = out + obase + off[ph];
        asm volatile("st.global.v8.f32 [%0], {%1,%2,%3,%4,%5,%6,%7,%8};"
                     :: "l"(op),
                        "f"(v[0][ph]),     "f"(v[0][4 + ph]),
                        "f"(v[1][ph]),     "f"(v[1][4 + ph]),
                        "f"(v[2][ph]),     "f"(v[2][4 + ph]),
                        "f"(v[3][ph]),     "f"(v[3][4 + ph])
                     : "memory");
    }
}

extern "C" void kernel_launch(void* const* d_in, const int* in_sizes, int n_in,
                              void* d_out, int out_size) {
    (void)n_in; (void)out_size;
    const float* in = (const float*)d_in[0];
    float* out = (float*)d_out;

    const long long total_threads = (long long)in_sizes[0] / 32;  // 32 floats/thread
    const int grid = (int)(total_threads / THREADS);              // exact: power of 2

    pixel_shuffle_kernel<<<grid, THREADS>>>(in, out);
}

// round 8
// speedup vs baseline: 1.0162x; 1.0162x over previous
#include <cuda_runtime.h>

// PixelShuffle / depth-to-space, R=2, feature-major grouping.
// in : [B=8, X=256, Y=256, C=256] fp32
// out: [B, 2X=512, 2Y=512, F=64]  fp32
// out[b, 2x+i, 2y+j, f] = in[b, x, y, 4f + 2i + j]
//
// Best-measured skeleton (R6: 8x LDG.128 front-batched, one-shot CTAs,
// default cache ops) with ADJACENT pixel pairing: thread handles pixels
// 2pp and 2pp+1 (same x, y = 2k/2k+1), so per i-phase a warp's 8 STG.128
// form a 2KB contiguous run (vs 1KB with far-split pairing) -> longer write
// bursts, fewer DRAM read/write turnarounds.
// Settled by measurement: .cs hints regress (L1 churn); persistent loop
// regresses (serializes MLP); v8 256-bit ops regress (L2 busy up, DRAM down).

static constexpr int X = 256;
static constexpr int Y = 256;
static constexpr int C = 256;   // = 64 features * 4
static constexpr int THREADS = 256;

__global__ void pixel_shuffle_kernel(const float4* __restrict__ in,
                                     float4* __restrict__ out) {
    const unsigned g = blockIdx.x * THREADS + threadIdx.x;

    const unsigned t = g & 15u;           // 16-channel chunk within pixel
    const unsigned pp = g >> 4;           // pixel-pair id; pixels 2pp, 2pp+1
    const unsigned p0 = pp * 2;           // b*65536 + x*256 + y (y even)

    const unsigned y = p0 & 255u;         // even; pair is (y, y+1), same x
    const unsigned x = (p0 >> 8) & 255u;
    const unsigned b = p0 >> 16;

    // ---- front-batch all 8 loads (MLP=8) ----
    // pixel p0: channels [16t,16t+16); pixel p0+1: same channels, +64 float4
    const float4* ip = in + (size_t)p0 * (C / 4) + t * 4;
    const float4 a0 = ip[0];
    const float4 a1 = ip[1];
    const float4 a2 = ip[2];
    const float4 a3 = ip[3];
    const float4 b0 = ip[64 + 0];
    const float4 b1 = ip[64 + 1];
    const float4 b2 = ip[64 + 2];
    const float4 b3 = ip[64 + 3];

    // ---- stores ----
    // out float4 index (pixel p0, i, j): ((b*512 + 2x+i)*512 + 2y+j)*16 + t
    // pixel p0+1 (y+1): j-coords 2y+2, 2y+3  -> +2*ROWJ from p0's base.
    const unsigned ROWI = (2 * Y) * 16;   // +i stride (one output X-row)
    const unsigned ROWJ = 16;             // +j stride (one output Y-row)
    const unsigned ob = (((b * (2 * X) + 2 * x) * (2 * Y)) + 2 * y) * 16 + t;

    // i=0 row: 4 consecutive output Y-rows (2y..2y+3) -> 2KB warp run
    out[ob]                   = make_float4(a0.x, a1.x, a2.x, a3.x); // p0,   j=0
    out[ob + ROWJ]            = make_float4(a0.y, a1.y, a2.y, a3.y); // p0,   j=1
    out[ob + 2 * ROWJ]        = make_float4(b0.x, b1.x, b2.x, b3.x); // p0+1, j=0
    out[ob + 3 * ROWJ]        = make_float4(b0.y, b1.y, b2.y, b3.y); // p0+1, j=1
    // i=1 row
    out[ob + ROWI]            = make_float4(a0.z, a1.z, a2.z, a3.z); // p0,   j=0
    out[ob + ROWI + ROWJ]     = make_float4(a0.w, a1.w, a2.w, a3.w); // p0,   j=1
    out[ob + ROWI + 2 * ROWJ] = make_float4(b0.z, b1.z, b2.z, b3.z); // p0+1, j=0
    out[ob + ROWI + 3 * ROWJ] = make_float4(b0.w, b1.w, b2.w, b3.w); // p0+1, j=1
}

extern "C" void kernel_launch(void* const* d_in, const int* in_sizes, int n_in,
                              void* d_out, int out_size) {
    (void)n_in; (void)out_size;
    const float4* in = (const float4*)d_in[0];
    float4* out = (float4*)d_out;

    const long long total_threads = (long long)in_sizes[0] / 32;  // 32 floats/thread
    const int grid = (int)(total_threads / THREADS);              // exact: power of 2

    pixel_shuffle_kernel<<<grid, THREADS>>>(in, out);
}

// round 9
// speedup vs baseline: 1.0266x; 1.0102x over previous
#include <cuda_runtime.h>

// PixelShuffle / depth-to-space, R=2, feature-major grouping.
// in : [B=8, X=256, Y=256, C=256] fp32
// out: [B, 2X=512, 2Y=512, F=64]  fp32
// out[b, 2x+i, 2y+j, f] = in[b, x, y, 4f + 2i + j]
//
// FINAL FAMILY. Thread handles adjacent pixel pair (2pp, 2pp+1): 8x LDG.128
// front-batched (warp = 4KB contiguous read), 8x STG.128 (per i-phase a warp
// writes a 2KB contiguous run of 4 output Y-rows). 128-thread CTAs for finest
// retirement granularity.
// Measured ceiling: DRAM 85-86% (HBM ~6.8TB/s) across five structural
// variants -> limiter is HBM read/write turnaround, not SM-side.
// Settled by measurement: .cs hints regress; persistent loop regresses;
// v8 256-bit ops regress; occupancy 49% vs 80% neutral; MLP 4 vs 8 neutral.

static constexpr int X = 256;
static constexpr int Y = 256;
static constexpr int C = 256;   // = 64 features * 4
static constexpr int THREADS = 128;

__global__ void pixel_shuffle_kernel(const float4* __restrict__ in,
                                     float4* __restrict__ out) {
    const unsigned g = blockIdx.x * THREADS + threadIdx.x;

    const unsigned t = g & 15u;           // 16-channel chunk within pixel
    const unsigned pp = g >> 4;           // pixel-pair id; pixels 2pp, 2pp+1
    const unsigned p0 = pp * 2;           // b*65536 + x*256 + y (y even)

    const unsigned y = p0 & 255u;         // even; pair is (y, y+1), same x
    const unsigned x = (p0 >> 8) & 255u;
    const unsigned b = p0 >> 16;

    // ---- front-batch all 8 loads (MLP=8) ----
    // pixel p0: channels [16t,16t+16); pixel p0+1: same channels, +64 float4
    const float4* ip = in + (size_t)p0 * (C / 4) + t * 4;
    const float4 a0 = ip[0];
    const float4 a1 = ip[1];
    const float4 a2 = ip[2];
    const float4 a3 = ip[3];
    const float4 b0 = ip[64 + 0];
    const float4 b1 = ip[64 + 1];
    const float4 b2 = ip[64 + 2];
    const float4 b3 = ip[64 + 3];

    // ---- stores ----
    // out float4 index (pixel p0, i, j): ((b*512 + 2x+i)*512 + 2y+j)*16 + t
    // pixel p0+1 (y+1): j-coords 2y+2, 2y+3  -> +2*ROWJ from p0's base.
    const unsigned ROWI = (2 * Y) * 16;   // +i stride (one output X-row)
    const unsigned ROWJ = 16;             // +j stride (one output Y-row)
    const unsigned ob = (((b * (2 * X) + 2 * x) * (2 * Y)) + 2 * y) * 16 + t;

    // i=0 row: 4 consecutive output Y-rows (2y..2y+3) -> 2KB warp run
    out[ob]                   = make_float4(a0.x, a1.x, a2.x, a3.x); // p0,   j=0
    out[ob + ROWJ]            = make_float4(a0.y, a1.y, a2.y, a3.y); // p0,   j=1
    out[ob + 2 * ROWJ]        = make_float4(b0.x, b1.x, b2.x, b3.x); // p0+1, j=0
    out[ob + 3 * ROWJ]        = make_float4(b0.y, b1.y, b2.y, b3.y); // p0+1, j=1
    // i=1 row
    out[ob + ROWI]            = make_float4(a0.z, a1.z, a2.z, a3.z); // p0,   j=0
    out[ob + ROWI + ROWJ]     = make_float4(a0.w, a1.w, a2.w, a3.w); // p0,   j=1
    out[ob + ROWI + 2 * ROWJ] = make_float4(b0.z, b1.z, b2.z, b3.z); // p0+1, j=0
    out[ob + ROWI + 3 * ROWJ] = make_float4(b0.w, b1.w, b2.w, b3.w); // p0+1, j=1
}

extern "C" void kernel_launch(void* const* d_in, const int* in_sizes, int n_in,
                              void* d_out, int out_size) {
    (void)n_in; (void)out_size;
    const float4* in = (const float4*)d_in[0];
    float4* out = (float4*)d_out;

    const long long total_threads = (long long)in_sizes[0] / 32;  // 32 floats/thread
    const int grid = (int)(total_threads / THREADS);              // exact: power of 2

    pixel_shuffle_kernel<<<grid, THREADS>>>(in, out);
}